// round 13
// baseline (speedup 1.0000x reference)
#include <cuda_runtime.h>
#include <cuda_fp16.h>
#include <cuda_bf16.h>

#define N_NODES 100000
#define N_EDGES 1600000
#define NH      4
#define HD      128
#define NEG_SLOPE 0.2f
#define CAP     64        // bucket capacity; Poisson(16) => P(deg>64) ~ 1e-20

// ---------------- scratch (device globals: allocation-free) ----------------
// g_cur is zero at every kernel_launch entry: zero-initialized at load, and
// node_kernel resets each node's cursor after consuming it.
__device__ __half g_fth[N_NODES * HD];   // projected features fp16 [N,128]
__device__ float  g_el [N_NODES * NH];   // left logits
__device__ float  g_er [N_NODES * NH];   // right logits
__device__ int    g_cur[N_NODES];        // per-node edge cursor (== degree)
__device__ int    g_bk [N_NODES * CAP];  // per-node src buckets

__device__ __forceinline__ float lrelu(float x) {
    return x > 0.f ? x : NEG_SLOPE * x;
}

// ---------------- fused persistent fp16 GEMM (+el/er) ∥ scatter ------------
// Blocks [0, GEMM_GRID): persistent GEMM over M-tiles of 64 rows,
// mma.m16n8k16.f16 fp32-accumulate, fragment-permuted smem (one 8B LDS per
// fragment). Blocks [GEMM_GRID, GRID): grid-stride bucket scatter. The two
// roles are data-independent; 3 CTAs/SM co-reside (2 gemm + 1 scatter).
#define MT        64
#define SMSH      144
#define NTILES    ((N_NODES + MT - 1) / MT)          // 1563
#define GEMM_GRID 296
#define SCAT_GRID 148
#define FUSED_GRID (GEMM_GRID + SCAT_GRID)           // 444 = 3/SM
#define GEMM_SMEM ((MT + 128) * SMSH * 2)            // 55296 B

__device__ __forceinline__ void store_perm_h(__half* rowp, int kbase, float4 v) {
    // kbase multiple of 4; permute so fragment halves (2t,2t+1,2t+8,2t+9)
    // of each 16-k group are contiguous
    int kb16 = kbase & ~15;
    int off  = ((kbase & 4) ? 8 : 0) + ((kbase & 8) ? 2 : 0);
    __half2* d = reinterpret_cast<__half2*>(rowp + kb16 + off);
    d[0] = __floats2half2_rn(v.x, v.y);
    d[2] = __floats2half2_rn(v.z, v.w);
}

__global__ __launch_bounds__(256, 3)
void fused_kernel(const float* __restrict__ feat, const float* __restrict__ W,
                  const float* __restrict__ attn_l, const float* __restrict__ attn_r,
                  const int* __restrict__ src, const int* __restrict__ dst) {
    const int tid = threadIdx.x;

    // ---------------- scatter role ----------------------------------------
    if (blockIdx.x >= GEMM_GRID) {
        int e0 = (blockIdx.x - GEMM_GRID) * 256 + tid;
        for (int e = e0; e < N_EDGES; e += SCAT_GRID * 256) {
            int d = dst[e];
            int pos = atomicAdd(&g_cur[d], 1);
            if (pos < CAP) g_bk[d * CAP + pos] = src[e];
        }
        return;
    }

    // ---------------- gemm role -------------------------------------------
    extern __shared__ __half sh[];
    __half* sF = sh;                 // [64 rows][SMSH]  feat tile (perm fp16)
    __half* sW = sh + MT * SMSH;     // [128 n  ][SMSH]  W (perm fp16)

    // load W once: [128n x 128k] -> sW[n][perm(k)]
    for (int i = tid; i < 4096; i += 256) {
        float4 w = reinterpret_cast<const float4*>(W)[i];
        int base = i * 4;
        int n = base >> 7, k = base & 127;
        store_perm_h(&sW[n * SMSH], k, w);
    }

    const int warp = tid >> 5, lane = tid & 31;
    const int g = lane >> 2, t = lane & 3;
    const int n0 = warp * 16;
    const int h   = warp >> 1;          // head of this warp's columns
    const int par = warp & 1;           // half of the head

    float2 alv[2], arv[2];
#pragma unroll
    for (int nt = 0; nt < 2; nt++) {
        alv[nt] = *reinterpret_cast<const float2*>(attn_l + n0 + nt * 8 + 2 * t);
        arv[nt] = *reinterpret_cast<const float2*>(attn_r + n0 + nt * 8 + 2 * t);
    }

    float* sPl = reinterpret_cast<float*>(sF);        // epilogue scratch overlay
    float* sPr = sPl + 512;

    for (int tile = blockIdx.x; tile < NTILES; tile += GEMM_GRID) {
        const int row0 = tile * MT;

        __syncthreads();   // prior epilogue scratch reads done before refill
        for (int i = tid; i < 2048; i += 256) {
            int base = i * 4;
            int r = base >> 7, k = base & 127;
            int gr = row0 + r;
            float4 f = (gr < N_NODES)
                     ? reinterpret_cast<const float4*>(feat)[gr * 32 + (k >> 2)]
                     : make_float4(0.f, 0.f, 0.f, 0.f);
            store_perm_h(&sF[r * SMSH], k, f);
        }
        __syncthreads();

        float c[4][2][4];
#pragma unroll
        for (int mt = 0; mt < 4; mt++)
#pragma unroll
            for (int nt = 0; nt < 2; nt++)
#pragma unroll
                for (int j = 0; j < 4; j++) c[mt][nt][j] = 0.f;

#pragma unroll
        for (int ks = 0; ks < 8; ks++) {
            const int ko = ks * 16;
            uint2 alo[4], ahi[4];
#pragma unroll
            for (int mt = 0; mt < 4; mt++) {
                alo[mt] = *reinterpret_cast<const uint2*>(&sF[(mt * 16 + g)     * SMSH + ko + 4 * t]);
                ahi[mt] = *reinterpret_cast<const uint2*>(&sF[(mt * 16 + g + 8) * SMSH + ko + 4 * t]);
            }
#pragma unroll
            for (int nt = 0; nt < 2; nt++) {
                uint2 b = *reinterpret_cast<const uint2*>(&sW[(n0 + nt * 8 + g) * SMSH + ko + 4 * t]);
#pragma unroll
                for (int mt = 0; mt < 4; mt++) {
                    asm volatile(
                        "mma.sync.aligned.m16n8k16.row.col.f32.f16.f16.f32 "
                        "{%0,%1,%2,%3}, {%4,%5,%6,%7}, {%8,%9}, {%0,%1,%2,%3};"
                        : "+f"(c[mt][nt][0]), "+f"(c[mt][nt][1]),
                          "+f"(c[mt][nt][2]), "+f"(c[mt][nt][3])
                        : "r"(alo[mt].x), "r"(ahi[mt].x),
                          "r"(alo[mt].y), "r"(ahi[mt].y),
                          "r"(b.x), "r"(b.y));
                }
            }
        }

        // store ft as fp16
#pragma unroll
        for (int mt = 0; mt < 4; mt++) {
            int r_lo = row0 + mt * 16 + g;
            int r_hi = r_lo + 8;
#pragma unroll
            for (int nt = 0; nt < 2; nt++) {
                int cc = n0 + nt * 8 + 2 * t;
                if (r_lo < N_NODES)
                    *reinterpret_cast<__half2*>(&g_fth[r_lo * HD + cc]) =
                        __floats2half2_rn(c[mt][nt][0], c[mt][nt][1]);
                if (r_hi < N_NODES)
                    *reinterpret_cast<__half2*>(&g_fth[r_hi * HD + cc]) =
                        __floats2half2_rn(c[mt][nt][2], c[mt][nt][3]);
            }
        }

        // el/er partials (registers only)
        float pll[4], plh[4], prl[4], prh[4];
#pragma unroll
        for (int mt = 0; mt < 4; mt++) {
            float a_lo = 0.f, a_hi = 0.f, b_lo = 0.f, b_hi = 0.f;
#pragma unroll
            for (int nt = 0; nt < 2; nt++) {
                a_lo += c[mt][nt][0] * alv[nt].x + c[mt][nt][1] * alv[nt].y;
                a_hi += c[mt][nt][2] * alv[nt].x + c[mt][nt][3] * alv[nt].y;
                b_lo += c[mt][nt][0] * arv[nt].x + c[mt][nt][1] * arv[nt].y;
                b_hi += c[mt][nt][2] * arv[nt].x + c[mt][nt][3] * arv[nt].y;
            }
#pragma unroll
            for (int off = 1; off <= 2; off <<= 1) {
                a_lo += __shfl_xor_sync(~0u, a_lo, off);
                a_hi += __shfl_xor_sync(~0u, a_hi, off);
                b_lo += __shfl_xor_sync(~0u, b_lo, off);
                b_hi += __shfl_xor_sync(~0u, b_hi, off);
            }
            pll[mt] = a_lo; plh[mt] = a_hi; prl[mt] = b_lo; prh[mt] = b_hi;
        }

        __syncthreads();               // all warps done reading sF this tile
        if (t == 0) {
#pragma unroll
            for (int mt = 0; mt < 4; mt++) {
                int row_lo = mt * 16 + g, row_hi = row_lo + 8;
                sPl[(row_lo * NH + h) * 2 + par] = pll[mt];
                sPl[(row_hi * NH + h) * 2 + par] = plh[mt];
                sPr[(row_lo * NH + h) * 2 + par] = prl[mt];
                sPr[(row_hi * NH + h) * 2 + par] = prh[mt];
            }
        }
        __syncthreads();
        {
            int row = tid >> 2, h2 = tid & 3;
            int gr = row0 + row;
            if (gr < N_NODES) {
                g_el[gr * NH + h2] = sPl[tid * 2] + sPl[tid * 2 + 1];
                g_er[gr * NH + h2] = sPr[tid * 2] + sPr[tid * 2 + 1];
            }
        }
    }
}

// ---------------- fused per-node softmax + aggregation ---------------------
// Also resets this node's cursor so g_cur is zero for the next launch.
__global__ __launch_bounds__(256)
void node_kernel(float* __restrict__ rst) {
    int gw   = (blockIdx.x * 256 + threadIdx.x) >> 5;
    int lane = threadIdx.x & 31;
    if (gw >= N_NODES) return;

    const int beg = gw * CAP;
    const int deg = min(g_cur[gw], CAP);
    if (lane == 0) g_cur[gw] = 0;          // restore invariant for next launch
    const int h    = lane >> 3;
    const int e_my = lane & 7;
    const float erh = __ldg(&g_er[gw * NH + h]);

    float4 acc = make_float4(0.f, 0.f, 0.f, 0.f);
    float wsum = 0.f;

    int base = 0;
    for (; base + 8 <= deg; base += 8) {
        int s_my = g_bk[beg + base + e_my];
        float a_val = __expf(lrelu(__ldg(&g_el[s_my * NH + h]) + erh));
        wsum += a_val;
#pragma unroll
        for (int e = 0; e < 8; e++) {
            float a = __shfl_sync(~0u, a_val, (lane & 24) | e);
            int   s = __shfl_sync(~0u, s_my, e);
            uint2 raw = *reinterpret_cast<const uint2*>(&g_fth[s * HD + lane * 4]);
            float2 f0 = __half22float2(*reinterpret_cast<__half2*>(&raw.x));
            float2 f1 = __half22float2(*reinterpret_cast<__half2*>(&raw.y));
            acc.x += a * f0.x; acc.y += a * f0.y;
            acc.z += a * f1.x; acc.w += a * f1.y;
        }
    }
    if (base < deg) {
        int nvalid = deg - base;
        float a_val = 0.f;
        int s_r = 0;
        if (e_my < nvalid) {
            s_r = g_bk[beg + base + e_my];
            a_val = __expf(lrelu(__ldg(&g_el[s_r * NH + h]) + erh));
        }
        wsum += a_val;
        for (int e = 0; e < nvalid; e++) {
            float a = __shfl_sync(~0u, a_val, (lane & 24) | e);
            int   s = __shfl_sync(~0u, s_r, e);
            uint2 raw = *reinterpret_cast<const uint2*>(&g_fth[s * HD + lane * 4]);
            float2 f0 = __half22float2(*reinterpret_cast<__half2*>(&raw.x));
            float2 f1 = __half22float2(*reinterpret_cast<__half2*>(&raw.y));
            acc.x += a * f0.x; acc.y += a * f0.y;
            acc.z += a * f1.x; acc.w += a * f1.y;
        }
    }

#pragma unroll
    for (int off = 1; off <= 4; off <<= 1)
        wsum += __shfl_xor_sync(~0u, wsum, off);
    float inv = (wsum > 0.f) ? __frcp_rn(wsum) : 0.f;

    acc.x *= inv; acc.y *= inv; acc.z *= inv; acc.w *= inv;
    *reinterpret_cast<float4*>(&rst[gw * HD + lane * 4]) = acc;
}

// ---------------- launch: 2 kernels, single stream -------------------------
extern "C" void kernel_launch(void* const* d_in, const int* in_sizes, int n_in,
                              void* d_out, int out_size) {
    const float* feat   = (const float*)d_in[0];
    const float* W      = (const float*)d_in[1];
    const float* attn_l = (const float*)d_in[2];
    const float* attn_r = (const float*)d_in[3];
    const int*   src    = (const int*)d_in[4];
    const int*   dst    = (const int*)d_in[5];
    float*       rst    = (float*)d_out;

    cudaFuncSetAttribute(fused_kernel, cudaFuncAttributeMaxDynamicSharedMemorySize,
                         GEMM_SMEM);

    fused_kernel<<<FUSED_GRID, 256, GEMM_SMEM>>>(feat, W, attn_l, attn_r, src, dst);
    node_kernel<<<(N_NODES * 32 + 255) / 256, 256>>>(rst);
}

// round 14
// speedup vs baseline: 2.2401x; 2.2401x over previous
#include <cuda_runtime.h>
#include <cuda_fp16.h>
#include <cuda_bf16.h>

#define N_NODES 100000
#define N_EDGES 1600000
#define NH      4
#define HD      128
#define NEG_SLOPE 0.2f
#define CAP     64        // bucket capacity; Poisson(16) => P(deg>64) ~ 1e-20

// ---------------- scratch (device globals: allocation-free) ----------------
__device__ __half g_fth[N_NODES * HD];   // projected features fp16 [N,128]
__device__ float  g_el [N_NODES * NH];   // left logits
__device__ float  g_er [N_NODES * NH];   // right logits
__device__ int    g_cur[N_NODES];        // per-node edge cursor (== degree)
__device__ int    g_bk [N_NODES * CAP];  // per-node src buckets

__device__ __forceinline__ float lrelu(float x) {
    return x > 0.f ? x : NEG_SLOPE * x;
}

// ---------------- explicit cursor zeroing (launch-local invariant) ---------
__global__ void zero_kernel() {
    int i = blockIdx.x * 256 + threadIdx.x;
    if (i < N_NODES) g_cur[i] = 0;
}

// ---------------- fused persistent fp16 GEMM (+el/er) ∥ scatter ------------
// Blocks [0, GEMM_GRID): persistent GEMM over M-tiles of 64 rows,
// mma.m16n8k16.f16 fp32-accumulate, fragment-permuted smem (one 8B LDS per
// fragment). Blocks [GEMM_GRID, GRID): grid-stride bucket scatter (cursors
// zeroed by zero_kernel, which precedes by stream order).
#define MT        64
#define SMSH      144
#define NTILES    ((N_NODES + MT - 1) / MT)          // 1563
#define GEMM_GRID 296
#define SCAT_GRID 148
#define FUSED_GRID (GEMM_GRID + SCAT_GRID)           // 444 = 3/SM
#define GEMM_SMEM ((MT + 128) * SMSH * 2)            // 55296 B

__device__ __forceinline__ void store_perm_h(__half* rowp, int kbase, float4 v) {
    int kb16 = kbase & ~15;
    int off  = ((kbase & 4) ? 8 : 0) + ((kbase & 8) ? 2 : 0);
    __half2* d = reinterpret_cast<__half2*>(rowp + kb16 + off);
    d[0] = __floats2half2_rn(v.x, v.y);
    d[2] = __floats2half2_rn(v.z, v.w);
}

__global__ __launch_bounds__(256, 3)
void fused_kernel(const float* __restrict__ feat, const float* __restrict__ W,
                  const float* __restrict__ attn_l, const float* __restrict__ attn_r,
                  const int* __restrict__ src, const int* __restrict__ dst) {
    const int tid = threadIdx.x;

    // ---------------- scatter role ----------------------------------------
    if (blockIdx.x >= GEMM_GRID) {
        int e0 = (blockIdx.x - GEMM_GRID) * 256 + tid;
        for (int e = e0; e < N_EDGES; e += SCAT_GRID * 256) {
            int d = dst[e];
            int pos = atomicAdd(&g_cur[d], 1);
            if (pos < CAP) g_bk[d * CAP + pos] = src[e];
        }
        return;
    }

    // ---------------- gemm role -------------------------------------------
    extern __shared__ __half sh[];
    __half* sF = sh;                 // [64 rows][SMSH]  feat tile (perm fp16)
    __half* sW = sh + MT * SMSH;     // [128 n  ][SMSH]  W (perm fp16)

    for (int i = tid; i < 4096; i += 256) {
        float4 w = reinterpret_cast<const float4*>(W)[i];
        int base = i * 4;
        int n = base >> 7, k = base & 127;
        store_perm_h(&sW[n * SMSH], k, w);
    }

    const int warp = tid >> 5, lane = tid & 31;
    const int g = lane >> 2, t = lane & 3;
    const int n0 = warp * 16;
    const int h   = warp >> 1;
    const int par = warp & 1;

    float2 alv[2], arv[2];
#pragma unroll
    for (int nt = 0; nt < 2; nt++) {
        alv[nt] = *reinterpret_cast<const float2*>(attn_l + n0 + nt * 8 + 2 * t);
        arv[nt] = *reinterpret_cast<const float2*>(attn_r + n0 + nt * 8 + 2 * t);
    }

    float* sPl = reinterpret_cast<float*>(sF);        // epilogue scratch overlay
    float* sPr = sPl + 512;

    for (int tile = blockIdx.x; tile < NTILES; tile += GEMM_GRID) {
        const int row0 = tile * MT;

        __syncthreads();
        for (int i = tid; i < 2048; i += 256) {
            int base = i * 4;
            int r = base >> 7, k = base & 127;
            int gr = row0 + r;
            float4 f = (gr < N_NODES)
                     ? reinterpret_cast<const float4*>(feat)[gr * 32 + (k >> 2)]
                     : make_float4(0.f, 0.f, 0.f, 0.f);
            store_perm_h(&sF[r * SMSH], k, f);
        }
        __syncthreads();

        float c[4][2][4];
#pragma unroll
        for (int mt = 0; mt < 4; mt++)
#pragma unroll
            for (int nt = 0; nt < 2; nt++)
#pragma unroll
                for (int j = 0; j < 4; j++) c[mt][nt][j] = 0.f;

#pragma unroll
        for (int ks = 0; ks < 8; ks++) {
            const int ko = ks * 16;
            uint2 alo[4], ahi[4];
#pragma unroll
            for (int mt = 0; mt < 4; mt++) {
                alo[mt] = *reinterpret_cast<const uint2*>(&sF[(mt * 16 + g)     * SMSH + ko + 4 * t]);
                ahi[mt] = *reinterpret_cast<const uint2*>(&sF[(mt * 16 + g + 8) * SMSH + ko + 4 * t]);
            }
#pragma unroll
            for (int nt = 0; nt < 2; nt++) {
                uint2 b = *reinterpret_cast<const uint2*>(&sW[(n0 + nt * 8 + g) * SMSH + ko + 4 * t]);
#pragma unroll
                for (int mt = 0; mt < 4; mt++) {
                    asm volatile(
                        "mma.sync.aligned.m16n8k16.row.col.f32.f16.f16.f32 "
                        "{%0,%1,%2,%3}, {%4,%5,%6,%7}, {%8,%9}, {%0,%1,%2,%3};"
                        : "+f"(c[mt][nt][0]), "+f"(c[mt][nt][1]),
                          "+f"(c[mt][nt][2]), "+f"(c[mt][nt][3])
                        : "r"(alo[mt].x), "r"(ahi[mt].x),
                          "r"(alo[mt].y), "r"(ahi[mt].y),
                          "r"(b.x), "r"(b.y));
                }
            }
        }

        // store ft as fp16
#pragma unroll
        for (int mt = 0; mt < 4; mt++) {
            int r_lo = row0 + mt * 16 + g;
            int r_hi = r_lo + 8;
#pragma unroll
            for (int nt = 0; nt < 2; nt++) {
                int cc = n0 + nt * 8 + 2 * t;
                if (r_lo < N_NODES)
                    *reinterpret_cast<__half2*>(&g_fth[r_lo * HD + cc]) =
                        __floats2half2_rn(c[mt][nt][0], c[mt][nt][1]);
                if (r_hi < N_NODES)
                    *reinterpret_cast<__half2*>(&g_fth[r_hi * HD + cc]) =
                        __floats2half2_rn(c[mt][nt][2], c[mt][nt][3]);
            }
        }

        // el/er partials
        float pll[4], plh[4], prl[4], prh[4];
#pragma unroll
        for (int mt = 0; mt < 4; mt++) {
            float a_lo = 0.f, a_hi = 0.f, b_lo = 0.f, b_hi = 0.f;
#pragma unroll
            for (int nt = 0; nt < 2; nt++) {
                a_lo += c[mt][nt][0] * alv[nt].x + c[mt][nt][1] * alv[nt].y;
                a_hi += c[mt][nt][2] * alv[nt].x + c[mt][nt][3] * alv[nt].y;
                b_lo += c[mt][nt][0] * arv[nt].x + c[mt][nt][1] * arv[nt].y;
                b_hi += c[mt][nt][2] * arv[nt].x + c[mt][nt][3] * arv[nt].y;
            }
#pragma unroll
            for (int off = 1; off <= 2; off <<= 1) {
                a_lo += __shfl_xor_sync(~0u, a_lo, off);
                a_hi += __shfl_xor_sync(~0u, a_hi, off);
                b_lo += __shfl_xor_sync(~0u, b_lo, off);
                b_hi += __shfl_xor_sync(~0u, b_hi, off);
            }
            pll[mt] = a_lo; plh[mt] = a_hi; prl[mt] = b_lo; prh[mt] = b_hi;
        }

        __syncthreads();
        if (t == 0) {
#pragma unroll
            for (int mt = 0; mt < 4; mt++) {
                int row_lo = mt * 16 + g, row_hi = row_lo + 8;
                sPl[(row_lo * NH + h) * 2 + par] = pll[mt];
                sPl[(row_hi * NH + h) * 2 + par] = plh[mt];
                sPr[(row_lo * NH + h) * 2 + par] = prl[mt];
                sPr[(row_hi * NH + h) * 2 + par] = prh[mt];
            }
        }
        __syncthreads();
        {
            int row = tid >> 2, h2 = tid & 3;
            int gr = row0 + row;
            if (gr < N_NODES) {
                g_el[gr * NH + h2] = sPl[tid * 2] + sPl[tid * 2 + 1];
                g_er[gr * NH + h2] = sPr[tid * 2] + sPr[tid * 2 + 1];
            }
        }
    }
}

// ---------------- fused per-node softmax + aggregation (R12 body) ----------
__global__ __launch_bounds__(256)
void node_kernel(float* __restrict__ rst) {
    int gw   = (blockIdx.x * 256 + threadIdx.x) >> 5;
    int lane = threadIdx.x & 31;
    if (gw >= N_NODES) return;

    const int beg = gw * CAP;
    const int deg = min(g_cur[gw], CAP);
    const int h    = lane >> 3;
    const int e_my = lane & 7;
    const float erh = __ldg(&g_er[gw * NH + h]);

    float4 acc = make_float4(0.f, 0.f, 0.f, 0.f);
    float wsum = 0.f;

    int base = 0;
    for (; base + 8 <= deg; base += 8) {
        int s_my = g_bk[beg + base + e_my];
        float a_val = __expf(lrelu(__ldg(&g_el[s_my * NH + h]) + erh));
        wsum += a_val;
#pragma unroll
        for (int e = 0; e < 8; e++) {
            float a = __shfl_sync(~0u, a_val, (lane & 24) | e);
            int   s = __shfl_sync(~0u, s_my, e);
            uint2 raw = *reinterpret_cast<const uint2*>(&g_fth[s * HD + lane * 4]);
            float2 f0 = __half22float2(*reinterpret_cast<__half2*>(&raw.x));
            float2 f1 = __half22float2(*reinterpret_cast<__half2*>(&raw.y));
            acc.x += a * f0.x; acc.y += a * f0.y;
            acc.z += a * f1.x; acc.w += a * f1.y;
        }
    }
    if (base < deg) {
        int nvalid = deg - base;
        float a_val = 0.f;
        int s_r = 0;
        if (e_my < nvalid) {
            s_r = g_bk[beg + base + e_my];
            a_val = __expf(lrelu(__ldg(&g_el[s_r * NH + h]) + erh));
        }
        wsum += a_val;
        for (int e = 0; e < nvalid; e++) {
            float a = __shfl_sync(~0u, a_val, (lane & 24) | e);
            int   s = __shfl_sync(~0u, s_r, e);
            uint2 raw = *reinterpret_cast<const uint2*>(&g_fth[s * HD + lane * 4]);
            float2 f0 = __half22float2(*reinterpret_cast<__half2*>(&raw.x));
            float2 f1 = __half22float2(*reinterpret_cast<__half2*>(&raw.y));
            acc.x += a * f0.x; acc.y += a * f0.y;
            acc.z += a * f1.x; acc.w += a * f1.y;
        }
    }

#pragma unroll
    for (int off = 1; off <= 4; off <<= 1)
        wsum += __shfl_xor_sync(~0u, wsum, off);
    float inv = (wsum > 0.f) ? __frcp_rn(wsum) : 0.f;

    acc.x *= inv; acc.y *= inv; acc.z *= inv; acc.w *= inv;
    *reinterpret_cast<float4*>(&rst[gw * HD + lane * 4]) = acc;
}

// ---------------- launch: 3 kernels, single stream -------------------------
extern "C" void kernel_launch(void* const* d_in, const int* in_sizes, int n_in,
                              void* d_out, int out_size) {
    const float* feat   = (const float*)d_in[0];
    const float* W      = (const float*)d_in[1];
    const float* attn_l = (const float*)d_in[2];
    const float* attn_r = (const float*)d_in[3];
    const int*   src    = (const int*)d_in[4];
    const int*   dst    = (const int*)d_in[5];
    float*       rst    = (float*)d_out;

    cudaFuncSetAttribute(fused_kernel, cudaFuncAttributeMaxDynamicSharedMemorySize,
                         GEMM_SMEM);

    zero_kernel<<<(N_NODES + 255) / 256, 256>>>();
    fused_kernel<<<FUSED_GRID, 256, GEMM_SMEM>>>(feat, W, attn_l, attn_r, src, dst);
    node_kernel<<<(N_NODES * 32 + 255) / 256, 256>>>(rst);
}

// round 15
// speedup vs baseline: 2.5060x; 1.1187x over previous
#include <cuda_runtime.h>
#include <cuda_fp16.h>
#include <cuda_bf16.h>

#define N_NODES 100000
#define N_EDGES 1600000
#define NH      4
#define HD      128
#define NEG_SLOPE 0.2f
#define CAP     64        // bucket capacity; Poisson(16) => P(deg>64) ~ 1e-20

// ---------------- scratch (device globals: allocation-free) ----------------
__device__ __half g_fth[N_NODES * HD];   // projected features fp16 [N,128]
__device__ float  g_el [N_NODES * NH];   // left logits
__device__ float  g_er [N_NODES * NH];   // right logits
__device__ int    g_cur[N_NODES];        // per-node edge cursor (== degree)
__device__ int    g_bk [N_NODES * CAP];  // per-node src buckets

__device__ __forceinline__ float lrelu(float x) {
    return x > 0.f ? x : NEG_SLOPE * x;
}

// ---------------- explicit cursor zeroing (launch-local invariant) ---------
__global__ void zero_kernel() {
    int i = blockIdx.x * 256 + threadIdx.x;
    if (i < N_NODES / 4)
        reinterpret_cast<int4*>(g_cur)[i] = make_int4(0, 0, 0, 0);
}

// ---------------- fused persistent fp16 GEMM (+el/er) ∥ scatter ------------
// Blocks [0, GEMM_GRID): persistent GEMM, mma.m16n8k16.f16 fp32-accumulate.
// Warp (mg, ng): mg = warp>>2 owns rows [mg*32, mg*32+32), ng = warp&3 owns
// cols [ng*32, ng*32+32) == head ng. Per k-step: 4 A LDS.64 + 4 B LDS.64 for
// 8 MMAs (was 10 LDS / 8 MMAs). Head-aligned warps -> el/er reduce fully
// in-warp, no smem scratch. Blocks [GEMM_GRID, GRID): grid-stride scatter.
#define MT        64
#define SMSH      144
#define NTILES    ((N_NODES + MT - 1) / MT)          // 1563
#define GEMM_GRID 296
#define SCAT_GRID 148
#define FUSED_GRID (GEMM_GRID + SCAT_GRID)           // 444 = 3/SM
#define GEMM_SMEM ((MT + 128) * SMSH * 2)            // 55296 B

__device__ __forceinline__ void store_perm_h(__half* rowp, int kbase, float4 v) {
    int kb16 = kbase & ~15;
    int off  = ((kbase & 4) ? 8 : 0) + ((kbase & 8) ? 2 : 0);
    __half2* d = reinterpret_cast<__half2*>(rowp + kb16 + off);
    d[0] = __floats2half2_rn(v.x, v.y);
    d[2] = __floats2half2_rn(v.z, v.w);
}

__global__ __launch_bounds__(256, 3)
void fused_kernel(const float* __restrict__ feat, const float* __restrict__ W,
                  const float* __restrict__ attn_l, const float* __restrict__ attn_r,
                  const int* __restrict__ src, const int* __restrict__ dst) {
    const int tid = threadIdx.x;

    // ---------------- scatter role ----------------------------------------
    if (blockIdx.x >= GEMM_GRID) {
        int e0 = (blockIdx.x - GEMM_GRID) * 256 + tid;
        for (int e = e0; e < N_EDGES; e += SCAT_GRID * 256) {
            int d = dst[e];
            int pos = atomicAdd(&g_cur[d], 1);
            if (pos < CAP) g_bk[d * CAP + pos] = src[e];
        }
        return;
    }

    // ---------------- gemm role -------------------------------------------
    extern __shared__ __half sh[];
    __half* sF = sh;                 // [64 rows][SMSH]
    __half* sW = sh + MT * SMSH;     // [128 n ][SMSH]

    for (int i = tid; i < 4096; i += 256) {
        float4 w = reinterpret_cast<const float4*>(W)[i];
        int base = i * 4;
        int n = base >> 7, k = base & 127;
        store_perm_h(&sW[n * SMSH], k, w);
    }

    const int warp = tid >> 5, lane = tid & 31;
    const int g = lane >> 2, t = lane & 3;
    const int mg = warp >> 2;           // row half: [mg*32, mg*32+32)
    const int ng = warp & 3;            // head / col group: [ng*32, +32)
    const int n0 = ng * 32;

    float2 alv[4], arv[4];
#pragma unroll
    for (int nt = 0; nt < 4; nt++) {
        alv[nt] = *reinterpret_cast<const float2*>(attn_l + n0 + nt * 8 + 2 * t);
        arv[nt] = *reinterpret_cast<const float2*>(attn_r + n0 + nt * 8 + 2 * t);
    }

    for (int tile = blockIdx.x; tile < NTILES; tile += GEMM_GRID) {
        const int row0 = tile * MT;

        __syncthreads();               // previous tile's smem reads complete
        for (int i = tid; i < 2048; i += 256) {
            int base = i * 4;
            int r = base >> 7, k = base & 127;
            int gr = row0 + r;
            float4 f = (gr < N_NODES)
                     ? reinterpret_cast<const float4*>(feat)[gr * 32 + (k >> 2)]
                     : make_float4(0.f, 0.f, 0.f, 0.f);
            store_perm_h(&sF[r * SMSH], k, f);
        }
        __syncthreads();

        float c[2][4][4];
#pragma unroll
        for (int mt = 0; mt < 2; mt++)
#pragma unroll
            for (int nt = 0; nt < 4; nt++)
#pragma unroll
                for (int j = 0; j < 4; j++) c[mt][nt][j] = 0.f;

#pragma unroll
        for (int ks = 0; ks < 8; ks++) {
            const int ko = ks * 16;
            uint2 alo[2], ahi[2];
#pragma unroll
            for (int mt = 0; mt < 2; mt++) {
                int rbase = mg * 32 + mt * 16;
                alo[mt] = *reinterpret_cast<const uint2*>(&sF[(rbase + g)     * SMSH + ko + 4 * t]);
                ahi[mt] = *reinterpret_cast<const uint2*>(&sF[(rbase + g + 8) * SMSH + ko + 4 * t]);
            }
#pragma unroll
            for (int nt = 0; nt < 4; nt++) {
                uint2 b = *reinterpret_cast<const uint2*>(&sW[(n0 + nt * 8 + g) * SMSH + ko + 4 * t]);
#pragma unroll
                for (int mt = 0; mt < 2; mt++) {
                    asm volatile(
                        "mma.sync.aligned.m16n8k16.row.col.f32.f16.f16.f32 "
                        "{%0,%1,%2,%3}, {%4,%5,%6,%7}, {%8,%9}, {%0,%1,%2,%3};"
                        : "+f"(c[mt][nt][0]), "+f"(c[mt][nt][1]),
                          "+f"(c[mt][nt][2]), "+f"(c[mt][nt][3])
                        : "r"(alo[mt].x), "r"(ahi[mt].x),
                          "r"(alo[mt].y), "r"(ahi[mt].y),
                          "r"(b.x), "r"(b.y));
                }
            }
        }

        // store ft as fp16 + fused el/er (warp owns head ng fully)
#pragma unroll
        for (int mt = 0; mt < 2; mt++) {
            int r_lo = row0 + mg * 32 + mt * 16 + g;
            int r_hi = r_lo + 8;
#pragma unroll
            for (int nt = 0; nt < 4; nt++) {
                int cc = n0 + nt * 8 + 2 * t;
                if (r_lo < N_NODES)
                    *reinterpret_cast<__half2*>(&g_fth[r_lo * HD + cc]) =
                        __floats2half2_rn(c[mt][nt][0], c[mt][nt][1]);
                if (r_hi < N_NODES)
                    *reinterpret_cast<__half2*>(&g_fth[r_hi * HD + cc]) =
                        __floats2half2_rn(c[mt][nt][2], c[mt][nt][3]);
            }

            float a_lo = 0.f, a_hi = 0.f, b_lo = 0.f, b_hi = 0.f;
#pragma unroll
            for (int nt = 0; nt < 4; nt++) {
                a_lo += c[mt][nt][0] * alv[nt].x + c[mt][nt][1] * alv[nt].y;
                a_hi += c[mt][nt][2] * alv[nt].x + c[mt][nt][3] * alv[nt].y;
                b_lo += c[mt][nt][0] * arv[nt].x + c[mt][nt][1] * arv[nt].y;
                b_hi += c[mt][nt][2] * arv[nt].x + c[mt][nt][3] * arv[nt].y;
            }
#pragma unroll
            for (int off = 1; off <= 2; off <<= 1) {
                a_lo += __shfl_xor_sync(~0u, a_lo, off);
                a_hi += __shfl_xor_sync(~0u, a_hi, off);
                b_lo += __shfl_xor_sync(~0u, b_lo, off);
                b_hi += __shfl_xor_sync(~0u, b_hi, off);
            }
            if (t == 0) {
                if (r_lo < N_NODES) { g_el[r_lo * NH + ng] = a_lo; g_er[r_lo * NH + ng] = b_lo; }
                if (r_hi < N_NODES) { g_el[r_hi * NH + ng] = a_hi; g_er[r_hi * NH + ng] = b_hi; }
            }
        }
    }
}

// ---------------- fused per-node softmax + aggregation ---------------------
// launch_bounds(256,8): cap regs at 32 for full 64-warp/SM occupancy.
__global__ __launch_bounds__(256, 8)
void node_kernel(float* __restrict__ rst) {
    int gw   = (blockIdx.x * 256 + threadIdx.x) >> 5;
    int lane = threadIdx.x & 31;
    if (gw >= N_NODES) return;

    const int beg = gw * CAP;
    const int deg = min(g_cur[gw], CAP);
    const int h    = lane >> 3;
    const int e_my = lane & 7;
    const float erh = __ldg(&g_er[gw * NH + h]);

    float4 acc = make_float4(0.f, 0.f, 0.f, 0.f);
    float wsum = 0.f;

    int base = 0;
    for (; base + 8 <= deg; base += 8) {
        int s_my = g_bk[beg + base + e_my];
        float a_val = __expf(lrelu(__ldg(&g_el[s_my * NH + h]) + erh));
        wsum += a_val;
#pragma unroll
        for (int e = 0; e < 8; e++) {
            float a = __shfl_sync(~0u, a_val, (lane & 24) | e);
            int   s = __shfl_sync(~0u, s_my, e);
            uint2 raw = *reinterpret_cast<const uint2*>(&g_fth[s * HD + lane * 4]);
            float2 f0 = __half22float2(*reinterpret_cast<__half2*>(&raw.x));
            float2 f1 = __half22float2(*reinterpret_cast<__half2*>(&raw.y));
            acc.x += a * f0.x; acc.y += a * f0.y;
            acc.z += a * f1.x; acc.w += a * f1.y;
        }
    }
    if (base < deg) {
        int nvalid = deg - base;
        float a_val = 0.f;
        int s_r = 0;
        if (e_my < nvalid) {
            s_r = g_bk[beg + base + e_my];
            a_val = __expf(lrelu(__ldg(&g_el[s_r * NH + h]) + erh));
        }
        wsum += a_val;
        for (int e = 0; e < nvalid; e++) {
            float a = __shfl_sync(~0u, a_val, (lane & 24) | e);
            int   s = __shfl_sync(~0u, s_r, e);
            uint2 raw = *reinterpret_cast<const uint2*>(&g_fth[s * HD + lane * 4]);
            float2 f0 = __half22float2(*reinterpret_cast<__half2*>(&raw.x));
            float2 f1 = __half22float2(*reinterpret_cast<__half2*>(&raw.y));
            acc.x += a * f0.x; acc.y += a * f0.y;
            acc.z += a * f1.x; acc.w += a * f1.y;
        }
    }

#pragma unroll
    for (int off = 1; off <= 4; off <<= 1)
        wsum += __shfl_xor_sync(~0u, wsum, off);
    float inv = (wsum > 0.f) ? __frcp_rn(wsum) : 0.f;

    acc.x *= inv; acc.y *= inv; acc.z *= inv; acc.w *= inv;
    *reinterpret_cast<float4*>(&rst[gw * HD + lane * 4]) = acc;
}

// ---------------- launch: 3 kernels, single stream -------------------------
extern "C" void kernel_launch(void* const* d_in, const int* in_sizes, int n_in,
                              void* d_out, int out_size) {
    const float* feat   = (const float*)d_in[0];
    const float* W      = (const float*)d_in[1];
    const float* attn_l = (const float*)d_in[2];
    const float* attn_r = (const float*)d_in[3];
    const int*   src    = (const int*)d_in[4];
    const int*   dst    = (const int*)d_in[5];
    float*       rst    = (float*)d_out;

    cudaFuncSetAttribute(fused_kernel, cudaFuncAttributeMaxDynamicSharedMemorySize,
                         GEMM_SMEM);

    zero_kernel<<<(N_NODES / 4 + 255) / 256, 256>>>();
    fused_kernel<<<FUSED_GRID, 256, GEMM_SMEM>>>(feat, W, attn_l, attn_r, src, dst);
    node_kernel<<<(N_NODES * 32 + 255) / 256, 256>>>(rst);
}